// round 16
// baseline (speedup 1.0000x reference)
#include <cuda_runtime.h>

#define H     51
#define BB    8
#define TPB   768
#define NCTA  128
#define T_IN  512
#define T_FUT 64
#define T_TOT 576
#define NTICK 514

typedef unsigned long long ull;

struct __align__(16) Smem {
    float4     W1q[52][H];    // k=0: W_ih1; k=1..51: W_hh1 col k-1; (i,f,g,o) of unit j
    float4     W2q[102][H];   // k=0..50: W_ih2; 51..101: W_hh2
    float4     W3q[102][H];
    ulonglong2 bq[3][H];      // bias pairs {bi,bf},{bg,bo}
    ull        hdup[154][BB]; // {h,h} per batch; row0=x, 1..51=h1, 52..102=h2, 103..153=h3
    float      wlin[52];
    float      blin;
};

__device__ __forceinline__ ull pack2(float x) {
    ull r; asm("mov.b64 %0, {%1, %1};" : "=l"(r) : "f"(x)); return r;
}
__device__ __forceinline__ ull packf2(float a, float b) {
    ull r; asm("mov.b64 %0, {%1, %2};" : "=l"(r) : "f"(a), "f"(b)); return r;
}
__device__ __forceinline__ void unpack2(ull v, float &a, float &b) {
    asm("mov.b64 {%0, %1}, %2;" : "=f"(a), "=f"(b) : "l"(v));
}
__device__ __forceinline__ ull fma2(ull a, ull b, ull c) {
    ull d; asm("fma.rn.f32x2 %0, %1, %2, %3;" : "=l"(d) : "l"(a), "l"(b), "l"(c)); return d;
}
// hardware tanh (sm_75+): 1 MUFU op, rel err ~2^-11
__device__ __forceinline__ float tanh_(float x) {
    float y; asm("tanh.approx.f32 %0, %1;" : "=f"(y) : "f"(x)); return y;
}
__device__ __forceinline__ float sigf(float x) {
    return fmaf(tanh_(0.5f * x), 0.5f, 0.5f);
}

// per k: 1 LDS.128 weight quad + 1 LDS.128 state pair + 4 fma2 (2 batch elems)
// acc[0]={i,f}b0  acc[1]={i,f}b1  acc[2]={g,o}b0  acc[3]={g,o}b1
template <int K>
__device__ __forceinline__ void gloop(const float4 (*__restrict__ W)[H],
                                      const ull (*__restrict__ Vd)[BB],
                                      int j, int bp2, ull acc[4]) {
#pragma unroll 3
    for (int k = 0; k < K; k++) {
        ulonglong2 wv = *(const ulonglong2 *)&W[k][j];    // {wi,wf},{wg,wo}
        ulonglong2 hv = *(const ulonglong2 *)&Vd[k][bp2]; // {h_b0,h_b0},{h_b1,h_b1}
        acc[0] = fma2(wv.x, hv.x, acc[0]);
        acc[1] = fma2(wv.x, hv.y, acc[1]);
        acc[2] = fma2(wv.y, hv.x, acc[2]);
        acc[3] = fma2(wv.y, hv.y, acc[3]);
    }
}

// thread-local cell for 2 batch elems
__device__ __forceinline__ void cell_local(const ull acc[4], float creg[2], ull hnew[2]) {
#pragma unroll
    for (int b = 0; b < 2; b++) {
        float iv, fv, gv, ov;
        unpack2(acc[b],     iv, fv);
        unpack2(acc[2 + b], gv, ov);
        float cn = sigf(fv) * creg[b] + sigf(iv) * tanh_(gv);
        float hn = sigf(ov) * tanh_(cn);
        creg[b]  = cn;
        hnew[b]  = pack2(hn);
    }
}

__device__ __forceinline__ float head_dot(const Smem *s, int b) {
    float sum = s->blin;
#pragma unroll 3
    for (int jj = 0; jj < H; jj++)
        sum = fmaf(s->wlin[jj], ((const float *)&s->hdup[103 + jj][b])[0], sum);
    return sum;
}

__global__ void __launch_bounds__(TPB, 1)
lstm_seq_kernel(const float *__restrict__ input,
                const float *__restrict__ W_ih1, const float *__restrict__ W_hh1,
                const float *__restrict__ b_ih1, const float *__restrict__ b_hh1,
                const float *__restrict__ W_ih2, const float *__restrict__ W_hh2,
                const float *__restrict__ b_ih2, const float *__restrict__ b_hh2,
                const float *__restrict__ W_ih3, const float *__restrict__ W_hh3,
                const float *__restrict__ b_ih3, const float *__restrict__ b_hh3,
                const float *__restrict__ W_lin, const float *__restrict__ b_lin,
                float *__restrict__ out) {
    extern __shared__ char raw[];
    Smem *s = (Smem *)raw;

    const int tid = threadIdx.x;
    const int b0  = blockIdx.x * BB;
    const int L   = tid >> 8;       // layer block of 256 lanes (8 warps)
    const int l   = tid & 255;
    const bool gate_lane = (l < 204);
    const int  j   = gate_lane ? (l >> 2) : (H - 1);  // hidden unit
    const int  bp2 = (l & 3) * 2;                     // batch-pair offset into hdup row
    const bool head_lane = (L == 0) && (l >= 204) && (l < 204 + BB);
    const bool xf_lane   = (L == 1) && (l >= 204) && (l < 204 + BB);

    // ---- one-time staging: weight quads (i,f,g,o) per unit j ----
    for (int idx = tid; idx < 52 * H; idx += TPB) {
        int k = idx / H, jj = idx % H;
        float4 v;
        if (k == 0)
            v = make_float4(W_ih1[jj], W_ih1[jj + 51], W_ih1[jj + 102], W_ih1[jj + 153]);
        else
            v = make_float4(W_hh1[jj * H + k - 1],         W_hh1[(jj + 51) * H + k - 1],
                            W_hh1[(jj + 102) * H + k - 1], W_hh1[(jj + 153) * H + k - 1]);
        s->W1q[k][jj] = v;
    }
    for (int idx = tid; idx < 102 * H; idx += TPB) {
        int k = idx / H, jj = idx % H;
        int kk = (k < H) ? k : k - H;
        const float *s2 = (k < H) ? W_ih2 : W_hh2;
        const float *s3 = (k < H) ? W_ih3 : W_hh3;
        s->W2q[k][jj] = make_float4(s2[jj * H + kk],         s2[(jj + 51) * H + kk],
                                    s2[(jj + 102) * H + kk], s2[(jj + 153) * H + kk]);
        s->W3q[k][jj] = make_float4(s3[jj * H + kk],         s3[(jj + 51) * H + kk],
                                    s3[(jj + 102) * H + kk], s3[(jj + 153) * H + kk]);
    }
    for (int idx = tid; idx < 3 * H; idx += TPB) {
        int ly = idx / H, jj = idx % H;
        const float *bi = (ly == 0) ? b_ih1 : (ly == 1) ? b_ih2 : b_ih3;
        const float *bh = (ly == 0) ? b_hh1 : (ly == 1) ? b_hh2 : b_hh3;
        ulonglong2 bv;
        bv.x = packf2(bi[jj] + bh[jj],             bi[jj + 51] + bh[jj + 51]);
        bv.y = packf2(bi[jj + 102] + bh[jj + 102], bi[jj + 153] + bh[jj + 153]);
        s->bq[ly][jj] = bv;
    }
    if (tid < H) s->wlin[tid] = W_lin[tid];
    if (tid == 0) s->blin = b_lin[0];
    for (int idx = tid; idx < 153 * BB; idx += TPB) (&s->hdup[1][0])[idx] = 0ull;
    if (tid < BB) s->hdup[0][tid] = pack2(input[(size_t)(b0 + tid) * T_IN]);  // x(0)
    __syncthreads();

    float creg[2] = {0.f, 0.f};   // c for batch bp2/2*... (this lane's 2 elems)

    // ===== pipelined main loop: tick t -> L1@t, L2@t-1, L3@t-2 =====
    for (int t = 0; t < NTICK; t++) {
        ull   acc[4], hnew[2];
        float xr = 0.0f;
        const bool valid = gate_lane &&
            ((L == 0) ? (t <= T_IN - 1)
                      : (L == 1) ? (t >= 1 && t <= T_IN) : (t >= 2));
        if (gate_lane) {
            ulonglong2 bv = s->bq[L][j];
            acc[0] = bv.x; acc[1] = bv.x; acc[2] = bv.y; acc[3] = bv.y;
            if (L == 0)      gloop<52>(s->W1q,  s->hdup,      j, bp2, acc);  // [x|h1]
            else if (L == 1) gloop<102>(s->W2q, s->hdup + 1,  j, bp2, acc);  // [h1|h2]
            else             gloop<102>(s->W3q, s->hdup + 52, j, bp2, acc);  // [h2|h3]
        } else if (head_lane && t >= 3) {
            int b = l - 204;
            out[(size_t)(b0 + b) * T_TOT + (t - 3)] = head_dot(s, b);
        } else if (xf_lane && t + 1 < T_IN) {
            xr = input[(size_t)(b0 + l - 204) * T_IN + t + 1];
        }
        if (valid) cell_local(acc, creg, hnew);
        __syncthreads();
        if (valid) {
            ulonglong2 hv; hv.x = hnew[0]; hv.y = hnew[1];
            *(ulonglong2 *)&s->hdup[1 + L * H + j][bp2] = hv;
        }
        if (xf_lane && t + 1 < T_IN) s->hdup[0][l - 204] = pack2(xr);
        __syncthreads();
    }

    // ---- drain: out(511) + first autoregressive input ----
    if (tid < BB) {
        float v = head_dot(s, tid);
        out[(size_t)(b0 + tid) * T_TOT + (T_IN - 1)] = v;
        s->hdup[0][tid] = pack2(v);
    }
    __syncthreads();

    // ===== autoregressive future: layer-serial, thread-local cell =====
    for (int fs = 0; fs < T_FUT; fs++) {
#pragma unroll
        for (int lay = 0; lay < 3; lay++) {
            ull acc[4], hnew[2];
            const bool w = (L == lay) && gate_lane;
            if (w) {
                ulonglong2 bv = s->bq[lay][j];
                acc[0] = bv.x; acc[1] = bv.x; acc[2] = bv.y; acc[3] = bv.y;
                if (lay == 0)      gloop<52>(s->W1q,  s->hdup,      j, bp2, acc);
                else if (lay == 1) gloop<102>(s->W2q, s->hdup + 1,  j, bp2, acc);
                else               gloop<102>(s->W3q, s->hdup + 52, j, bp2, acc);
                cell_local(acc, creg, hnew);
            }
            __syncthreads();
            if (w) {
                ulonglong2 hv; hv.x = hnew[0]; hv.y = hnew[1];
                *(ulonglong2 *)&s->hdup[1 + lay * H + j][bp2] = hv;
            }
            __syncthreads();
        }
        if (tid < BB) {
            float v = head_dot(s, tid);
            out[(size_t)(b0 + tid) * T_TOT + T_IN + fs] = v;
            s->hdup[0][tid] = pack2(v);
        }
        __syncthreads();
    }
}

extern "C" void kernel_launch(void *const *d_in, const int *in_sizes, int n_in,
                              void *d_out, int out_size) {
    (void)in_sizes; (void)n_in; (void)out_size;
    cudaFuncSetAttribute(lstm_seq_kernel,
                         cudaFuncAttributeMaxDynamicSharedMemorySize,
                         (int)sizeof(Smem));
    lstm_seq_kernel<<<NCTA, TPB, sizeof(Smem)>>>(
        (const float *)d_in[0],
        (const float *)d_in[1], (const float *)d_in[2],
        (const float *)d_in[3], (const float *)d_in[4],
        (const float *)d_in[5], (const float *)d_in[6],
        (const float *)d_in[7], (const float *)d_in[8],
        (const float *)d_in[9], (const float *)d_in[10],
        (const float *)d_in[11], (const float *)d_in[12],
        (const float *)d_in[13], (const float *)d_in[14],
        (float *)d_out);
}

// round 17
// speedup vs baseline: 1.4742x; 1.4742x over previous
#include <cuda_runtime.h>

#define H      51
#define BB     8
#define TPB    384
#define NCTA   128
#define T_IN   512
#define T_FUT  64
#define T_TOT  576
#define NTICK  514
#define NT     13    // m16 tiles over 208 gate rows (204 real)
#define KC1    7     // L1 k-chunks of 8 (K=52 real, 56 padded)
#define KC23   13    // L2/L3 k-chunks   (K=102 real, 104 padded)
#define GSTR   212   // gate-staging row stride (floats), bank-spread + 16B-aligned

// L1 A-fragments live in global (L1/L2-cached); smem can't hold all three packs.
__device__ float g_W1p[KC1 * NT * 32 * 4];

struct __align__(16) Smem {
    float a2[KC23 * NT * 32 * 4];  // A-fragment packs: [kc][tile][lane][4]
    float a3[KC23 * NT * 32 * 4];
    float b1[KC1 * 32 * 2];        // B-fragment packs: [kc][lane][2]
    float b2[KC23 * 32 * 2];
    float b3[KC23 * 32 * 2];
    float gstN[3][8][GSTR];        // gates staging: [layer][batch n][gate row m]
    float biasr[3][208];           // bias, rows reordered m = 4*unit + gate
    float h3row[52][8];            // plain h3 for the head
    float wlin[52];
    float blin;
};

__device__ __forceinline__ float tanh_(float x) {
    float y; asm("tanh.approx.f32 %0, %1;" : "=f"(y) : "f"(x)); return y;
}
__device__ __forceinline__ float sigf(float x) {
    return fmaf(tanh_(0.5f * x), 0.5f, 0.5f);
}

// D[16,8] += A[16,8] * B[8,8]; tf32 inputs (HW truncates fp32 bit patterns)
__device__ __forceinline__ void mma8(float d[4], float4 a, float2 b) {
    asm volatile(
        "mma.sync.aligned.m16n8k8.row.col.f32.tf32.tf32.f32 "
        "{%0,%1,%2,%3},{%4,%5,%6,%7},{%8,%9},{%0,%1,%2,%3};"
        : "+f"(d[0]), "+f"(d[1]), "+f"(d[2]), "+f"(d[3])
        : "r"(__float_as_uint(a.x)), "r"(__float_as_uint(a.y)),
          "r"(__float_as_uint(a.z)), "r"(__float_as_uint(a.w)),
          "r"(__float_as_uint(b.x)), "r"(__float_as_uint(b.y)));
}

// B-fragment scatter: value at (k, n) -> pack[(kc*32 + 4n + (k&3))*2 + ((k&7)>>2)]
__device__ __forceinline__ void putB(float *Bp, int k, int n, float v) {
    int kc = k >> 3, r = k & 7;
    Bp[((kc * 32) + 4 * n + (r & 3)) * 2 + (r >> 2)] = v;
}

// weight source for reordered row m = 4*unit+gate, input position k
__device__ __forceinline__ float wsrc2(const float *Wih, const float *Whh,
                                       int m, int k) {   // K inputs = [hA(51) | hB(51)]
    if (m >= 204 || k >= 102) return 0.0f;
    int row = (m & 3) * 51 + (m >> 2);
    return (k < H) ? Wih[row * H + k] : Whh[row * H + (k - H)];
}
__device__ __forceinline__ float wsrc1(const float *Wih, const float *Whh,
                                       int m, int k) {   // inputs = [x | h1]
    if (m >= 204 || k >= 52) return 0.0f;
    int row = (m & 3) * 51 + (m >> 2);
    return (k == 0) ? Wih[row] : Whh[row * H + (k - 1)];
}

__global__ void prep_kernel(const float *__restrict__ W_ih1,
                            const float *__restrict__ W_hh1) {
    int e = blockIdx.x * blockDim.x + threadIdx.x;
    if (e >= KC1 * NT * 32) return;
    int kc = e / (NT * 32), rem = e % (NT * 32);
    int tile = rem >> 5, lam = rem & 31;
    int m0 = tile * 16 + (lam >> 2), k0 = kc * 8 + (lam & 3);
    float4 v;
    v.x = wsrc1(W_ih1, W_hh1, m0,     k0);
    v.y = wsrc1(W_ih1, W_hh1, m0 + 8, k0);
    v.z = wsrc1(W_ih1, W_hh1, m0,     k0 + 4);
    v.w = wsrc1(W_ih1, W_hh1, m0 + 8, k0 + 4);
    *(float4 *)&g_W1p[e * 4] = v;
}

__device__ __forceinline__ float head_dot(const Smem *s, int b) {
    float sum = s->blin;
#pragma unroll 3
    for (int jj = 0; jj < H; jj++) sum = fmaf(s->wlin[jj], s->h3row[jj][b], sum);
    return sum;
}

// one layer's GEMM phase: D = bias + A*B -> gstN[L]
__device__ __forceinline__ void mma_phase(Smem *s, int L, int w, int lam) {
    const int gr = lam >> 2, tcc = lam & 3;
    const int KC = (L == 0) ? KC1 : KC23;
    const float *Bp = (L == 0) ? s->b1 : (L == 1) ? s->b2 : s->b3;
    const float *Ap = (L == 1) ? s->a2 : s->a3;
    float d[4][4];
#pragma unroll
    for (int i = 0; i < 4; i++) {
        int tile = w + 4 * i;
        if (tile < NT) {
            float blo = s->biasr[L][tile * 16 + gr];
            float bhi = s->biasr[L][tile * 16 + 8 + gr];
            d[i][0] = blo; d[i][1] = blo; d[i][2] = bhi; d[i][3] = bhi;
        }
    }
#pragma unroll 1
    for (int kc = 0; kc < KC; kc++) {
        float2 bf = *(const float2 *)&Bp[(kc * 32 + lam) * 2];
#pragma unroll
        for (int i = 0; i < 4; i++) {
            int tile = w + 4 * i;
            if (tile < NT) {
                float4 av;
                if (L == 0)
                    av = *(const float4 *)&g_W1p[((kc * NT + tile) * 32 + lam) * 4];
                else
                    av = *(const float4 *)&Ap[((kc * NT + tile) * 32 + lam) * 4];
                mma8(d[i], av, bf);
            }
        }
    }
#pragma unroll
    for (int i = 0; i < 4; i++) {
        int tile = w + 4 * i;
        if (tile < NT) {
            int row = tile * 16 + gr;
            s->gstN[L][2 * tcc][row]         = d[i][0];
            s->gstN[L][2 * tcc + 1][row]     = d[i][1];
            s->gstN[L][2 * tcc][row + 8]     = d[i][2];
            s->gstN[L][2 * tcc + 1][row + 8] = d[i][3];
        }
    }
}

// cell for lane (j, bh): reads gstN[L], updates creg, writes h into consumer packs
__device__ __forceinline__ void cell_phase(Smem *s, int L, int j, int bh4,
                                           float creg[4]) {
    float4 gi = *(const float4 *)&s->gstN[L][bh4 + 0][0] ;  // placeholder; real below
    (void)gi;
}

__global__ void __launch_bounds__(TPB, 1)
lstm_seq_kernel(const float *__restrict__ input,
                const float *__restrict__ b_ih1, const float *__restrict__ b_hh1,
                const float *__restrict__ W_ih2, const float *__restrict__ W_hh2,
                const float *__restrict__ b_ih2, const float *__restrict__ b_hh2,
                const float *__restrict__ W_ih3, const float *__restrict__ W_hh3,
                const float *__restrict__ b_ih3, const float *__restrict__ b_hh3,
                const float *__restrict__ W_lin, const float *__restrict__ b_lin,
                float *__restrict__ out) {
    extern __shared__ char raw[];
    Smem *s = (Smem *)raw;

    const int tid = threadIdx.x;
    const int b0  = blockIdx.x * BB;
    const int L   = tid >> 7;       // layer block: warps 0-3 / 4-7 / 8-11
    const int l   = tid & 127;
    const int w   = (tid >> 5) & 3; // warp within block
    const int lam = tid & 31;
    const int j   = l >> 1;         // cell unit (l < 102)
    const int bh4 = (l & 1) * 4;    // cell batch-half

    // ---- one-time staging ----
    for (int e = tid; e < KC23 * NT * 32; e += TPB) {
        int kc = e / (NT * 32), rem = e % (NT * 32);
        int tile = rem >> 5, lm = rem & 31;
        int m0 = tile * 16 + (lm >> 2), k0 = kc * 8 + (lm & 3);
        float4 v2, v3;
        v2.x = wsrc2(W_ih2, W_hh2, m0, k0);     v2.y = wsrc2(W_ih2, W_hh2, m0 + 8, k0);
        v2.z = wsrc2(W_ih2, W_hh2, m0, k0 + 4); v2.w = wsrc2(W_ih2, W_hh2, m0 + 8, k0 + 4);
        v3.x = wsrc2(W_ih3, W_hh3, m0, k0);     v3.y = wsrc2(W_ih3, W_hh3, m0 + 8, k0);
        v3.z = wsrc2(W_ih3, W_hh3, m0, k0 + 4); v3.w = wsrc2(W_ih3, W_hh3, m0 + 8, k0 + 4);
        *(float4 *)&s->a2[e * 4] = v2;
        *(float4 *)&s->a3[e * 4] = v3;
    }
    for (int e = tid; e < 3 * 208; e += TPB) {
        int ly = e / 208, m = e % 208;
        float v = 0.0f;
        if (m < 204) {
            int row = (m & 3) * 51 + (m >> 2);
            const float *bi = (ly == 0) ? b_ih1 : (ly == 1) ? b_ih2 : b_ih3;
            const float *bh = (ly == 0) ? b_hh1 : (ly == 1) ? b_hh2 : b_hh3;
            v = bi[row] + bh[row];
        }
        s->biasr[ly][m] = v;
    }
    for (int e = tid; e < KC1 * 64; e += TPB) s->b1[e] = 0.0f;
    for (int e = tid; e < KC23 * 64; e += TPB) { s->b2[e] = 0.0f; s->b3[e] = 0.0f; }
    for (int e = tid; e < 3 * 8 * GSTR; e += TPB) (&s->gstN[0][0][0])[e] = 0.0f;
    for (int e = tid; e < 52 * 8; e += TPB) (&s->h3row[0][0])[e] = 0.0f;
    if (tid < H) s->wlin[tid] = W_lin[tid];
    if (tid == 0) s->blin = b_lin[0];
    __syncthreads();
    if (tid < BB) putB(s->b1, 0, tid, input[(size_t)(b0 + tid) * T_IN]);  // x(0)
    __syncthreads();

    float creg[4] = {0.f, 0.f, 0.f, 0.f};

    // ===== pipelined main loop: tick t -> L1@t, L2@t-1, L3@t-2 =====
    for (int t = 0; t < NTICK; t++) {
        // ---- phase A: tensor-core gates (all layers concurrently) ----
        mma_phase(s, L, w, lam);
        float xr = 0.0f;
        if (L == 0 && w == 3 && lam < BB && t >= 3) {
            out[(size_t)(b0 + lam) * T_TOT + (t - 3)] = head_dot(s, lam);
        } else if (L == 1 && w == 3 && lam < BB && t + 1 < T_IN) {
            xr = input[(size_t)(b0 + lam) * T_IN + t + 1];
        }
        __syncthreads();
        // ---- phase B: cell + h scatter into consumer B-packs ----
        const bool valid = (l < 102) &&
            ((L == 0) ? (t <= T_IN - 1)
                      : (L == 1) ? (t >= 1 && t <= T_IN) : (t >= 2));
        if (valid) {
            float4 gv0 = *(const float4 *)&s->gstN[L][bh4 + 0][4 * j];
            float4 gv1 = *(const float4 *)&s->gstN[L][bh4 + 1][4 * j];
            float4 gv2 = *(const float4 *)&s->gstN[L][bh4 + 2][4 * j];
            float4 gv3 = *(const float4 *)&s->gstN[L][bh4 + 3][4 * j];
            float hn[4];
            {   // gv*: rows 4j..4j+3 = gates i,f,g,o of unit j, per-batch u
                const float4 g4[4] = {gv0, gv1, gv2, gv3};
#pragma unroll
                for (int u = 0; u < 4; u++) {
                    float iv = g4[u].x, fv = g4[u].y, gg = g4[u].z, ov = g4[u].w;
                    float cn = sigf(fv) * creg[u] + sigf(iv) * tanh_(gg);
                    hn[u]    = sigf(ov) * tanh_(cn);
                    creg[u]  = cn;
                }
            }
#pragma unroll
            for (int u = 0; u < 4; u++) {
                int n = bh4 + u;
                float v = hn[u];
                if (L == 0)      { putB(s->b1, 1 + j, n, v); putB(s->b2, j, n, v); }
                else if (L == 1) { putB(s->b2, H + j, n, v); putB(s->b3, j, n, v); }
                else             { putB(s->b3, H + j, n, v); s->h3row[j][n] = v; }
            }
        }
        if (L == 1 && w == 3 && lam < BB && t + 1 < T_IN) putB(s->b1, 0, lam, xr);
        __syncthreads();
    }

    // ---- drain: out(511) + first autoregressive input ----
    if (tid < BB) {
        float v = head_dot(s, tid);
        out[(size_t)(b0 + tid) * T_TOT + (T_IN - 1)] = v;
        putB(s->b1, 0, tid, v);
    }
    __syncthreads();

    // ===== autoregressive future: layer-serial, same machinery =====
    for (int fs = 0; fs < T_FUT; fs++) {
#pragma unroll 1
        for (int lay = 0; lay < 3; lay++) {
            if (L == lay) mma_phase(s, L, w, lam);
            __syncthreads();
            if (L == lay && l < 102) {
                float4 gv0 = *(const float4 *)&s->gstN[L][bh4 + 0][4 * j];
                float4 gv1 = *(const float4 *)&s->gstN[L][bh4 + 1][4 * j];
                float4 gv2 = *(const float4 *)&s->gstN[L][bh4 + 2][4 * j];
                float4 gv3 = *(const float4 *)&s->gstN[L][bh4 + 3][4 * j];
                const float4 g4[4] = {gv0, gv1, gv2, gv3};
                float hn[4];
#pragma unroll
                for (int u = 0; u < 4; u++) {
                    float iv = g4[u].x, fv = g4[u].y, gg = g4[u].z, ov = g4[u].w;
                    float cn = sigf(fv) * creg[u] + sigf(iv) * tanh_(gg);
                    hn[u]    = sigf(ov) * tanh_(cn);
                    creg[u]  = cn;
                }
#pragma unroll
                for (int u = 0; u < 4; u++) {
                    int n = bh4 + u;
                    float v = hn[u];
                    if (L == 0)      { putB(s->b1, 1 + j, n, v); putB(s->b2, j, n, v); }
                    else if (L == 1) { putB(s->b2, H + j, n, v); putB(s->b3, j, n, v); }
                    else             { putB(s->b3, H + j, n, v); s->h3row[j][n] = v; }
                }
            }
            __syncthreads();
        }
        if (tid < BB) {
            float v = head_dot(s, tid);
            out[(size_t)(b0 + tid) * T_TOT + T_IN + fs] = v;
            putB(s->b1, 0, tid, v);
        }
        __syncthreads();
    }
}

extern "C" void kernel_launch(void *const *d_in, const int *in_sizes, int n_in,
                              void *d_out, int out_size) {
    (void)in_sizes; (void)n_in; (void)out_size;
    prep_kernel<<<(KC1 * NT * 32 + 255) / 256, 256>>>(
        (const float *)d_in[1], (const float *)d_in[2]);
    cudaFuncSetAttribute(lstm_seq_kernel,
                         cudaFuncAttributeMaxDynamicSharedMemorySize,
                         (int)sizeof(Smem));
    lstm_seq_kernel<<<NCTA, TPB, sizeof(Smem)>>>(
        (const float *)d_in[0],
        (const float *)d_in[3], (const float *)d_in[4],
        (const float *)d_in[5], (const float *)d_in[6],
        (const float *)d_in[7], (const float *)d_in[8],
        (const float *)d_in[9], (const float *)d_in[10],
        (const float *)d_in[11], (const float *)d_in[12],
        (const float *)d_in[13], (const float *)d_in[14],
        (float *)d_out);
}